// round 12
// baseline (speedup 1.0000x reference)
#include <cuda_runtime.h>
#include <cuda_fp16.h>
#include <cstdint>

// CRF: energy[B,T,U] = x[B,T,D] @ w[D,U] + bias + start*lb + end*rb
// GEMM M=32768 K=1024 N=128 fp32 via single-pass fp16 mma.sync.
// R12 = R11 + 4-stage B ring with cp.async issued BEFORE compute (fill
// overlaps HMMA), inner unroll x4 (compile-time stage idx), f16x2 cvt.

#define M_TOT 32768
#define K_TOT 1024
#define N_TOT 128
#define T_LEN 512
#define BM 128
#define BK 32
#define NCHUNK (K_TOT / BK)   // 32
#define NTILES (M_TOT / BM)   // 256
#define NTHREADS 256

#define ROWB 80                       // row stride; ldmatrix conflict-free
#define TILE_BYTES (128 * ROWB)       // 10240
#define A_ST(i) ((i) * TILE_BYTES)            // 2 A stages
#define B_ST(j) (2 * TILE_BYTES + (j) * TILE_BYTES)   // 4 B stages
#define SM_BIAS (6 * TILE_BYTES)      // 61440
#define SM_LB   (SM_BIAS + 512)
#define SM_RB   (SM_BIAS + 1024)
#define SM_TOTAL (SM_BIAS + 1536)     // 62976 (dynamic)

__device__ __forceinline__ uint32_t smem_u32(const void* p) {
    uint32_t a;
    asm("{ .reg .u64 t; cvta.to.shared.u64 t, %1; cvt.u32.u64 %0, t; }" : "=r"(a) : "l"(p));
    return a;
}

__device__ __forceinline__ void ldsm_x4(uint32_t (&r)[4], uint32_t addr) {
    asm volatile("ldmatrix.sync.aligned.m8n8.x4.shared.b16 {%0,%1,%2,%3}, [%4];"
                 : "=r"(r[0]), "=r"(r[1]), "=r"(r[2]), "=r"(r[3]) : "r"(addr));
}

__device__ __forceinline__ void mma16816(float (&c)[4], const uint32_t (&a)[4],
                                         uint32_t b0, uint32_t b1) {
    asm volatile(
        "mma.sync.aligned.m16n8k16.row.col.f32.f16.f16.f32 "
        "{%0,%1,%2,%3}, {%4,%5,%6,%7}, {%8,%9}, {%0,%1,%2,%3};"
        : "+f"(c[0]), "+f"(c[1]), "+f"(c[2]), "+f"(c[3])
        : "r"(a[0]), "r"(a[1]), "r"(a[2]), "r"(a[3]), "r"(b0), "r"(b1));
}

// pack: low half <- lo, high half <- hi (single F2FP instruction)
__device__ __forceinline__ uint32_t cvt2h(float lo, float hi) {
    uint32_t r;
    asm("cvt.rn.f16x2.f32 %0, %1, %2;" : "=r"(r) : "f"(hi), "f"(lo));
    return r;
}

__device__ __forceinline__ uint32_t pk(__half a, __half b) {
    __half2 t = __halves2half2(a, b);
    return *reinterpret_cast<uint32_t*>(&t);
}

#define CP_ASYNC16(dst, src) \
    asm volatile("cp.async.cg.shared.global [%0], [%1], 16;" \
                 :: "r"((uint32_t)(dst)), "l"(src) : "memory")
#define CP_COMMIT() asm volatile("cp.async.commit_group;" ::: "memory")
#define CP_WAIT(n)  asm volatile("cp.async.wait_group %0;" :: "n"(n) : "memory")

// w transposed to [N, K] fp16 (K-major, "col" operand for mma.sync)
__device__ __align__(16) __half g_wh[N_TOT * K_TOT];

// coalesced transpose prep: 32x32 smem tiles
__global__ __launch_bounds__(256)
void prep_w_kernel(const float* __restrict__ w) {
    __shared__ __half t[32][33];
    const int tx = threadIdx.x & 31, ty0 = threadIdx.x >> 5;   // 32 x 8
    const int kb = blockIdx.x * 32, nb = blockIdx.y * 32;
#pragma unroll
    for (int j = 0; j < 4; j++) {
        int k = ty0 + j * 8;
        t[tx][k] = __float2half(w[(size_t)(kb + k) * N_TOT + nb + tx]);
    }
    __syncthreads();
#pragma unroll
    for (int j = 0; j < 4; j++) {
        int n = ty0 + j * 8;
        g_wh[(size_t)(nb + n) * K_TOT + kb + tx] = t[n][tx];
    }
}

__global__ __launch_bounds__(NTHREADS, 2)
void crf_mma_kernel(const float* __restrict__ x, const int* __restrict__ mask,
                    const float* __restrict__ bias, const float* __restrict__ lb,
                    const float* __restrict__ rb, float* __restrict__ out) {
    extern __shared__ __align__(128) char sm[];
    const uint32_t smb = smem_u32(sm);

    const int tid = threadIdx.x;
    const int wid = tid >> 5, lane = tid & 31;
    const int wm = wid & 1, wn = wid >> 1;      // 2 M-warps x 4 N-warps, 64x32
    const int rowBase = blockIdx.x * BM;

    if (tid < N_TOT) {
        *(float*)(sm + SM_BIAS + tid * 4) = bias[tid];
        *(float*)(sm + SM_LB + tid * 4) = lb[tid];
        *(float*)(sm + SM_RB + tid * 4) = rb[tid];
    }

    float acc[4][4][4];   // [mt][nt][frag]
#pragma unroll
    for (int i = 0; i < 4; i++)
#pragma unroll
        for (int j = 0; j < 4; j++)
#pragma unroll
            for (int v = 0; v < 4; v++) acc[i][j][v] = 0.0f;

    const int grp = lane >> 3, lr = lane & 7;
    const uint32_t aRow = wm * 64 + (grp & 1) * 8 + lr;
    const uint32_t aKof = (grp >> 1) * 8;
    const uint32_t bRow = wn * 32 + (grp >> 1) * 8 + lr;
    const uint32_t bKof = (grp & 1) * 8;

    float4 aR[4];

    auto load_regs = [&](int c) {       // A chunk -> regs (2 ahead), evict-first
        const int kt = c * BK;
#pragma unroll
        for (int i = 0; i < 4; i++) {
            int idx = i * NTHREADS + tid;
            int r = idx >> 3, c4 = idx & 7;          // 128 rows x 8 float4
            aR[i] = __ldcs(reinterpret_cast<const float4*>(
                x + (size_t)(rowBase + r) * K_TOT + kt + c4 * 4));
        }
    };
    auto sts_A = [&](int buf) {         // convert + store A
        char* base = sm + A_ST(buf);
#pragma unroll
        for (int i = 0; i < 4; i++) {
            int idx = i * NTHREADS + tid;
            int r = idx >> 3, c4 = idx & 7;
            float4 v = aR[i];
            uint2 hh;
            hh.x = cvt2h(v.x, v.y);
            hh.y = cvt2h(v.z, v.w);
            *(uint2*)(base + (uint32_t)(r * ROWB + c4 * 8)) = hh;
        }
    };
    auto cpasync_B = [&](int c, int st) {   // B chunk -> smem stage st
        const int kt = c * BK;
        const uint32_t base = smb + B_ST(st);
#pragma unroll
        for (int i = 0; i < 2; i++) {
            int idx = i * NTHREADS + tid;
            int n = idx >> 2, q = idx & 3;           // 128 rows x 4 x 16B
            CP_ASYNC16(base + (uint32_t)(n * ROWB + q * 16),
                       g_wh + (size_t)n * K_TOT + kt + q * 8);
        }
        CP_COMMIT();
    };

    // ---- prologue: B(0..2) async; A(0) -> stage 0; A(1) -> regs ----
    cpasync_B(0, 0);
    cpasync_B(1, 1);
    cpasync_B(2, 2);
    load_regs(0);
    sts_A(0);
    load_regs(1);
    CP_WAIT(2);        // B(0) complete (B1,B2 may pend)
    __syncthreads();

#pragma unroll 1
    for (int cc = 0; cc < NCHUNK / 4; cc++) {
#pragma unroll
        for (int u = 0; u < 4; u++) {
            const int c = cc * 4 + u;
            const uint32_t aSt = smb + A_ST(u & 1);
            const uint32_t bSt = smb + B_ST(u);

            if (c + 1 < NCHUNK) sts_A((u + 1) & 1);      // aR holds A(c+1)
            if (c + 2 < NCHUNK) load_regs(c + 2);
            if (c + 3 < NCHUNK) cpasync_B(c + 3, (u + 3) & 3);
            else CP_COMMIT();                             // keep group count

            // ---- compute chunk c: 2 k16-steps ----
#pragma unroll
            for (int ks = 0; ks < 2; ks++) {
                uint32_t af[4][4];
#pragma unroll
                for (int mt = 0; mt < 4; mt++)
                    ldsm_x4(af[mt], aSt + (aRow + mt * 16) * ROWB + (ks * 16 + aKof) * 2);
                uint32_t bf[2][4];
#pragma unroll
                for (int np = 0; np < 2; np++)
                    ldsm_x4(bf[np], bSt + (bRow + np * 16) * ROWB + (ks * 16 + bKof) * 2);
#pragma unroll
                for (int mt = 0; mt < 4; mt++)
#pragma unroll
                    for (int np = 0; np < 2; np++) {
                        mma16816(acc[mt][2 * np + 0], af[mt], bf[np][0], bf[np][1]);
                        mma16816(acc[mt][2 * np + 1], af[mt], bf[np][2], bf[np][3]);
                    }
            }

            CP_WAIT(2);          // B(c+1) complete (c+2, c+3 may pend)
            __syncthreads();
        }
    }

    // ---- fused epilogue ----
    const float* sb = (const float*)(sm + SM_BIAS);
    const float* sl = (const float*)(sm + SM_LB);
    const float* sr = (const float*)(sm + SM_RB);
    const int colBase = wn * 32 + (lane & 3) * 2;
#pragma unroll
    for (int mt = 0; mt < 4; mt++) {
#pragma unroll
        for (int h = 0; h < 2; h++) {
            int m = rowBase + wm * 64 + mt * 16 + h * 8 + (lane >> 2);
            int bb = m >> 9, t = m & (T_LEN - 1);
            const int* mrow = mask + bb * T_LEN;
            int mv = mrow[t];
            int prev = t ? mrow[t - 1] : 0;
            int nxt = (t < T_LEN - 1) ? mrow[t + 1] : 0;
            float sf = (mv > prev) ? 1.0f : 0.0f;
            float ef = (nxt > mv) ? 1.0f : 0.0f;
            float* orow = out + (size_t)m * N_TOT;
#pragma unroll
            for (int nt = 0; nt < 4; nt++) {
                int col = colBase + nt * 8;
                float2 v;
                v.x = acc[mt][nt][h * 2 + 0] + sb[col] + sf * sl[col] + ef * sr[col];
                v.y = acc[mt][nt][h * 2 + 1] + sb[col + 1] + sf * sl[col + 1] + ef * sr[col + 1];
                *reinterpret_cast<float2*>(orow + col) = v;
            }
        }
    }
}

extern "C" void kernel_launch(void* const* d_in, const int* in_sizes, int n_in,
                              void* d_out, int out_size) {
    const float* x    = (const float*)d_in[0];  // [B,T,D]
    const int*   mask = (const int*)d_in[1];    // [B,T]
    const float* w    = (const float*)d_in[2];  // [D,U]
    const float* bias = (const float*)d_in[3];
    const float* lb   = (const float*)d_in[4];
    const float* rb   = (const float*)d_in[5];
    float* out = (float*)d_out;

    dim3 pg(K_TOT / 32, N_TOT / 32);
    prep_w_kernel<<<pg, 256>>>(w);

    static int configured = 0;
    if (!configured) {
        cudaFuncSetAttribute(crf_mma_kernel,
                             cudaFuncAttributeMaxDynamicSharedMemorySize, SM_TOTAL);
        configured = 1;
    }
    crf_mma_kernel<<<NTILES, NTHREADS, SM_TOTAL>>>(x, mask, bias, lb, rb, out);
}